// round 1
// baseline (speedup 1.0000x reference)
#include <cuda_runtime.h>
#include <math.h>

#define TT 1024
#define BB 8
#define CC 1024
#define NHD 16
#define HDIM 64
#define MR (BB*TT)   // 8192 tokens

// ---- static scratch (no allocations allowed) ----
__device__ float g_h  [MR*CC];        // 32 MB  LN output (reused for ln2)
__device__ float g_qkv[MR*3*CC];      // 96 MB
__device__ float g_pos[NHD*TT*TT];    // 64 MB  [h][t][s]
__device__ float g_y  [MR*CC];        // 32 MB  attention output
__device__ float g_x2 [MR*CC];        // 32 MB  residual after attn
__device__ float g_act[MR*4*CC];      // 128 MB MLP hidden

// ============================================================
// LayerNorm: one block per row (1024 cols), 256 threads
// ============================================================
__global__ __launch_bounds__(256) void ln_kernel(
    const float* __restrict__ x, const float* __restrict__ g,
    const float* __restrict__ b, float* __restrict__ out)
{
    int row = blockIdx.x;
    int tid = threadIdx.x;
    const float4* x4 = reinterpret_cast<const float4*>(x + (size_t)row * CC);
    float4 xv = x4[tid];
    float s  = xv.x + xv.y + xv.z + xv.w;
    float sq = xv.x*xv.x + xv.y*xv.y + xv.z*xv.z + xv.w*xv.w;
#pragma unroll
    for (int o = 16; o > 0; o >>= 1) {
        s  += __shfl_xor_sync(0xffffffffu, s,  o);
        sq += __shfl_xor_sync(0xffffffffu, sq, o);
    }
    __shared__ float ss[8], ssq[8];
    int w = tid >> 5, l = tid & 31;
    if (l == 0) { ss[w] = s; ssq[w] = sq; }
    __syncthreads();
    if (tid == 0) {
        float a = 0.f, c = 0.f;
#pragma unroll
        for (int i = 0; i < 8; i++) { a += ss[i]; c += ssq[i]; }
        ss[0] = a; ssq[0] = c;
    }
    __syncthreads();
    float mu  = ss[0] * (1.0f / CC);
    float var = ssq[0] * (1.0f / CC) - mu * mu;
    float inv = rsqrtf(var + 1e-5f);
    float4 gv = reinterpret_cast<const float4*>(g)[tid];
    float4 bv = reinterpret_cast<const float4*>(b)[tid];
    float4 ov;
    ov.x = (xv.x - mu) * inv * gv.x + bv.x;
    ov.y = (xv.y - mu) * inv * gv.y + bv.y;
    ov.z = (xv.z - mu) * inv * gv.z + bv.z;
    ov.w = (xv.w - mu) * inv * gv.w + bv.w;
    reinterpret_cast<float4*>(out + (size_t)row * CC)[tid] = ov;
}

// ============================================================
// SGEMM: C[M,N] = A[M,K] @ B[K,N] + bias, epilogue variants.
// 128x128 block tile, K-step 8, 256 threads, 8x8 microtile.
// EPI: 0 = +bias, 1 = gelu(+bias), 2 = +bias + residual
// ============================================================
__device__ __forceinline__ float gelu_f(float v) {
    float c = 0.7978845608028654f;
    return 0.5f * v * (1.0f + tanhf(c * (v + 0.044715f * v * v * v)));
}

template <int EPI>
__global__ __launch_bounds__(256) void sgemm_kernel(
    const float* __restrict__ A, const float* __restrict__ B,
    const float* __restrict__ bias, const float* __restrict__ res,
    float* __restrict__ C, int M, int N, int K)
{
    __shared__ float As[8][128];
    __shared__ float Bs[8][128];
    int bx = blockIdx.x, by = blockIdx.y;
    int tid = threadIdx.x;
    int tx = tid & 15, ty = tid >> 4;

    float acc[8][8];
#pragma unroll
    for (int i = 0; i < 8; i++)
#pragma unroll
        for (int j = 0; j < 8; j++) acc[i][j] = 0.f;

    const float* Aptr = A + (size_t)(by * 128) * K;
    const float* Bptr = B + (size_t)bx * 128;

    int aRow = tid >> 1;
    int aCol = (tid & 1) * 4;
    int bRow = tid >> 5;
    int bCol = (tid & 31) * 4;

    for (int k0 = 0; k0 < K; k0 += 8) {
        float4 a4 = *reinterpret_cast<const float4*>(Aptr + (size_t)aRow * K + k0 + aCol);
        As[aCol + 0][aRow] = a4.x;
        As[aCol + 1][aRow] = a4.y;
        As[aCol + 2][aRow] = a4.z;
        As[aCol + 3][aRow] = a4.w;
        float4 b4 = *reinterpret_cast<const float4*>(Bptr + (size_t)(k0 + bRow) * N + bCol);
        *reinterpret_cast<float4*>(&Bs[bRow][bCol]) = b4;
        __syncthreads();
#pragma unroll
        for (int kk = 0; kk < 8; kk++) {
            float a[8], bv[8];
            *reinterpret_cast<float4*>(a)      = *reinterpret_cast<const float4*>(&As[kk][ty * 4]);
            *reinterpret_cast<float4*>(a + 4)  = *reinterpret_cast<const float4*>(&As[kk][64 + ty * 4]);
            *reinterpret_cast<float4*>(bv)     = *reinterpret_cast<const float4*>(&Bs[kk][tx * 4]);
            *reinterpret_cast<float4*>(bv + 4) = *reinterpret_cast<const float4*>(&Bs[kk][64 + tx * 4]);
#pragma unroll
            for (int i = 0; i < 8; i++)
#pragma unroll
                for (int j = 0; j < 8; j++)
                    acc[i][j] += a[i] * bv[j];
        }
        __syncthreads();
    }

#pragma unroll
    for (int i = 0; i < 8; i++) {
        int r = by * 128 + ((i < 4) ? (ty * 4 + i) : (64 + ty * 4 + i - 4));
#pragma unroll
        for (int jh = 0; jh < 2; jh++) {
            int c0 = bx * 128 + jh * 64 + tx * 4;
            float4 bi = *reinterpret_cast<const float4*>(bias + c0);
            float v0 = acc[i][jh * 4 + 0] + bi.x;
            float v1 = acc[i][jh * 4 + 1] + bi.y;
            float v2 = acc[i][jh * 4 + 2] + bi.z;
            float v3 = acc[i][jh * 4 + 3] + bi.w;
            if (EPI == 1) {
                v0 = gelu_f(v0); v1 = gelu_f(v1); v2 = gelu_f(v2); v3 = gelu_f(v3);
            }
            if (EPI == 2) {
                float4 rv = *reinterpret_cast<const float4*>(res + (size_t)r * N + c0);
                v0 += rv.x; v1 += rv.y; v2 += rv.z; v3 += rv.w;
            }
            float4 ov; ov.x = v0; ov.y = v1; ov.z = v2; ov.w = v3;
            *reinterpret_cast<float4*>(C + (size_t)r * N + c0) = ov;
        }
    }
}

// ============================================================
// Positional bias projection: pos[h][t][s] = bias[t][s][:]·W_bias[:,h] + b_bias[h]
// ============================================================
__global__ __launch_bounds__(256) void posbias_kernel(
    const float* __restrict__ bias, const float* __restrict__ Wb,
    const float* __restrict__ bb, float* __restrict__ pos)
{
    __shared__ float w[16][17];
    __shared__ float bbs[16];
    int tid = threadIdx.x;
    w[tid >> 4][tid & 15] = Wb[tid];
    if (tid < 16) bbs[tid] = bb[tid];
    __syncthreads();
    int idx = blockIdx.x * 256 + tid;   // t*T + s
    const float4* bp = reinterpret_cast<const float4*>(bias + (size_t)idx * 16);
    float4 b0 = bp[0], b1 = bp[1], b2 = bp[2], b3 = bp[3];
    float f[16] = { b0.x, b0.y, b0.z, b0.w, b1.x, b1.y, b1.z, b1.w,
                    b2.x, b2.y, b2.z, b2.w, b3.x, b3.y, b3.z, b3.w };
#pragma unroll
    for (int h = 0; h < 16; h++) {
        float acc = bbs[h];
#pragma unroll
        for (int ff = 0; ff < 16; ff++) acc += f[ff] * w[ff][h];
        pos[(size_t)h * TT * TT + idx] = acc;
    }
}

// ============================================================
// Flash-style attention: block = (b, h, 64-row tile of t), 256 threads.
// Streams K/V in 64-wide s-tiles; online softmax; never spills scores.
// ============================================================
__global__ __launch_bounds__(256) void attn_kernel(
    const float* __restrict__ qkv, const float* __restrict__ pos,
    float* __restrict__ y)
{
    extern __shared__ float sm[];
    float* qT = sm;            // [d][r] 64x64
    float* kT = sm + 4096;     // [d][j] 64x64
    float* vS = sm + 8192;     // [s][d] 64x64
    float* sS = sm + 12288;    // [r][j] 64x64
    float* mS = sm + 16384;    // 64 running max
    float* lS = sm + 16448;    // 64 running sum
    float* scS = sm + 16512;   // 64 rescale factor

    int blk = blockIdx.x;
    int t0 = (blk & 15) << 6;
    int h  = (blk >> 4) & 15;
    int b  = blk >> 8;
    int tid = threadIdx.x;
    int tx = tid & 15, ty = tid >> 4;
    int tr = tid >> 2;            // 0..63 (loader / softmax row)
    int dc = (tid & 3) << 4;      // 0,16,32,48

    const float* qb = qkv + (size_t)(b * TT) * 3072 + h * 64;

    // load Q tile transposed
#pragma unroll
    for (int l2 = 0; l2 < 4; l2++) {
        float4 v4 = *reinterpret_cast<const float4*>(qb + (size_t)(t0 + tr) * 3072 + dc + l2 * 4);
        int d = dc + l2 * 4;
        qT[(d + 0) * 64 + tr] = v4.x;
        qT[(d + 1) * 64 + tr] = v4.y;
        qT[(d + 2) * 64 + tr] = v4.z;
        qT[(d + 3) * 64 + tr] = v4.w;
    }
    if (tid < 64) { mS[tid] = -1e30f; lS[tid] = 0.f; }

    float o[4][4];
#pragma unroll
    for (int i = 0; i < 4; i++)
#pragma unroll
        for (int j = 0; j < 4; j++) o[i][j] = 0.f;

    const float* posb = pos + ((size_t)h * TT + t0) * TT;

    for (int s0 = 0; s0 < TT; s0 += 64) {
        const float* kb = qb + 1024 + (size_t)s0 * 3072;
        const float* vb = qb + 2048 + (size_t)s0 * 3072;
#pragma unroll
        for (int l2 = 0; l2 < 4; l2++) {
            int d = dc + l2 * 4;
            float4 k4 = *reinterpret_cast<const float4*>(kb + (size_t)tr * 3072 + d);
            kT[(d + 0) * 64 + tr] = k4.x;
            kT[(d + 1) * 64 + tr] = k4.y;
            kT[(d + 2) * 64 + tr] = k4.z;
            kT[(d + 3) * 64 + tr] = k4.w;
            float4 v4 = *reinterpret_cast<const float4*>(vb + (size_t)tr * 3072 + d);
            *reinterpret_cast<float4*>(&vS[tr * 64 + d]) = v4;
        }
        __syncthreads();

        // S = Q Kᵀ (4x4 microtile per thread)
        float sa[4][4];
#pragma unroll
        for (int i = 0; i < 4; i++)
#pragma unroll
            for (int j = 0; j < 4; j++) sa[i][j] = 0.f;
#pragma unroll 8
        for (int d = 0; d < 64; d++) {
            float4 a4 = *reinterpret_cast<const float4*>(&qT[d * 64 + ty * 4]);
            float4 b4 = *reinterpret_cast<const float4*>(&kT[d * 64 + tx * 4]);
            float a[4] = { a4.x, a4.y, a4.z, a4.w };
            float bb2[4] = { b4.x, b4.y, b4.z, b4.w };
#pragma unroll
            for (int i = 0; i < 4; i++)
#pragma unroll
                for (int j = 0; j < 4; j++)
                    sa[i][j] += a[i] * bb2[j];
        }
#pragma unroll
        for (int i = 0; i < 4; i++) {
            int r = ty * 4 + i;
            float4 p4 = *reinterpret_cast<const float4*>(posb + (size_t)r * TT + s0 + tx * 4);
            sS[r * 64 + tx * 4 + 0] = sa[i][0] * 0.125f + p4.x;
            sS[r * 64 + tx * 4 + 1] = sa[i][1] * 0.125f + p4.y;
            sS[r * 64 + tx * 4 + 2] = sa[i][2] * 0.125f + p4.z;
            sS[r * 64 + tx * 4 + 3] = sa[i][3] * 0.125f + p4.w;
        }
        __syncthreads();

        // online softmax: 4 threads per row, 16 cols each
        {
            float vals[16];
            *reinterpret_cast<float4*>(vals)      = *reinterpret_cast<const float4*>(&sS[tr * 64 + dc]);
            *reinterpret_cast<float4*>(vals + 4)  = *reinterpret_cast<const float4*>(&sS[tr * 64 + dc + 4]);
            *reinterpret_cast<float4*>(vals + 8)  = *reinterpret_cast<const float4*>(&sS[tr * 64 + dc + 8]);
            *reinterpret_cast<float4*>(vals + 12) = *reinterpret_cast<const float4*>(&sS[tr * 64 + dc + 12]);
            float mx = vals[0];
#pragma unroll
            for (int q = 1; q < 16; q++) mx = fmaxf(mx, vals[q]);
            mx = fmaxf(mx, __shfl_xor_sync(0xffffffffu, mx, 1));
            mx = fmaxf(mx, __shfl_xor_sync(0xffffffffu, mx, 2));
            float m_old = mS[tr];
            float m_new = fmaxf(m_old, mx);
            float sum = 0.f;
#pragma unroll
            for (int q = 0; q < 16; q++) { vals[q] = __expf(vals[q] - m_new); sum += vals[q]; }
            *reinterpret_cast<float4*>(&sS[tr * 64 + dc])      = *reinterpret_cast<float4*>(vals);
            *reinterpret_cast<float4*>(&sS[tr * 64 + dc + 4])  = *reinterpret_cast<float4*>(vals + 4);
            *reinterpret_cast<float4*>(&sS[tr * 64 + dc + 8])  = *reinterpret_cast<float4*>(vals + 8);
            *reinterpret_cast<float4*>(&sS[tr * 64 + dc + 12]) = *reinterpret_cast<float4*>(vals + 12);
            sum += __shfl_xor_sync(0xffffffffu, sum, 1);
            sum += __shfl_xor_sync(0xffffffffu, sum, 2);  // sync point: all reads of mS/lS done
            if ((tid & 3) == 0) {
                float sc = __expf(m_old - m_new);
                scS[tr] = sc;
                lS[tr] = lS[tr] * sc + sum;
                mS[tr] = m_new;
            }
        }
        __syncthreads();

        // O = O*scale + P V
#pragma unroll
        for (int i = 0; i < 4; i++) {
            float sc = scS[ty * 4 + i];
            o[i][0] *= sc; o[i][1] *= sc; o[i][2] *= sc; o[i][3] *= sc;
        }
#pragma unroll 4
        for (int s = 0; s < 64; s++) {
            float4 v4 = *reinterpret_cast<const float4*>(&vS[s * 64 + tx * 4]);
#pragma unroll
            for (int i = 0; i < 4; i++) {
                float p = sS[(ty * 4 + i) * 64 + s];
                o[i][0] += p * v4.x;
                o[i][1] += p * v4.y;
                o[i][2] += p * v4.z;
                o[i][3] += p * v4.w;
            }
        }
        __syncthreads();
    }

    // normalize and write y[b,t, h*64 + d]
#pragma unroll
    for (int i = 0; i < 4; i++) {
        int r = ty * 4 + i;
        float inv = 1.0f / lS[r];
        float4 ov;
        ov.x = o[i][0] * inv; ov.y = o[i][1] * inv;
        ov.z = o[i][2] * inv; ov.w = o[i][3] * inv;
        *reinterpret_cast<float4*>(
            &y[((size_t)(b * TT + t0 + r)) * CC + h * 64 + tx * 4]) = ov;
    }
}

// ============================================================
extern "C" void kernel_launch(void* const* d_in, const int* in_sizes, int n_in,
                              void* d_out, int out_size)
{
    const float* x      = (const float*)d_in[0];
    const float* bias   = (const float*)d_in[1];
    const float* ln1_g  = (const float*)d_in[2];
    const float* ln1_b  = (const float*)d_in[3];
    const float* W_attn = (const float*)d_in[4];
    const float* b_attn = (const float*)d_in[5];
    const float* W_o    = (const float*)d_in[6];
    const float* b_o    = (const float*)d_in[7];
    const float* W_bias = (const float*)d_in[8];
    const float* b_bias = (const float*)d_in[9];
    const float* ln2_g  = (const float*)d_in[10];
    const float* ln2_b  = (const float*)d_in[11];
    const float* W_fc   = (const float*)d_in[12];
    const float* b_fc   = (const float*)d_in[13];
    const float* W_fc2  = (const float*)d_in[14];
    const float* b_fc2  = (const float*)d_in[15];
    float* out = (float*)d_out;

    float *ph, *pqkv, *ppos, *py, *px2, *pact;
    cudaGetSymbolAddress((void**)&ph,   g_h);
    cudaGetSymbolAddress((void**)&pqkv, g_qkv);
    cudaGetSymbolAddress((void**)&ppos, g_pos);
    cudaGetSymbolAddress((void**)&py,   g_y);
    cudaGetSymbolAddress((void**)&px2,  g_x2);
    cudaGetSymbolAddress((void**)&pact, g_act);

    cudaFuncSetAttribute(attn_kernel, cudaFuncAttributeMaxDynamicSharedMemorySize, 66304);

    // 1) LN1
    ln_kernel<<<MR, 256>>>(x, ln1_g, ln1_b, ph);
    // 2) QKV = h @ W_attn + b_attn
    sgemm_kernel<0><<<dim3(3072 / 128, MR / 128), 256>>>(ph, W_attn, b_attn, nullptr, pqkv, MR, 3072, 1024);
    // 3) positional bias projection
    posbias_kernel<<<(TT * TT) / 256, 256>>>(bias, W_bias, b_bias, ppos);
    // 4) attention
    attn_kernel<<<BB * NHD * (TT / 64), 256, 66304>>>(pqkv, ppos, py);
    // 5) x2 = x + y @ W_o + b_o
    sgemm_kernel<2><<<dim3(1024 / 128, MR / 128), 256>>>(py, W_o, b_o, x, px2, MR, 1024, 1024);
    // 6) LN2
    ln_kernel<<<MR, 256>>>(px2, ln2_g, ln2_b, ph);
    // 7) act = gelu(h2 @ W_fc + b_fc)
    sgemm_kernel<1><<<dim3(4096 / 128, MR / 128), 256>>>(ph, W_fc, b_fc, nullptr, pact, MR, 4096, 1024);
    // 8) out = x2 + act @ W_fc2 + b_fc2
    sgemm_kernel<2><<<dim3(1024 / 128, MR / 128), 256>>>(pact, W_fc2, b_fc2, px2, out, MR, 1024, 4096);
}

// round 4
// speedup vs baseline: 1.7102x; 1.7102x over previous
#include <cuda_runtime.h>
#include <cuda_bf16.h>
#include <math.h>
#include <stdint.h>

#define TT 1024
#define BB 8
#define CC 1024
#define NHD 16
#define MR (BB*TT)   // 8192 tokens

// ---- static scratch (no allocations allowed) ----
__device__ __nv_bfloat16 g_sa  [(size_t)MR*3*CC];      // 48MB  split activations [hi|lo|hi]
__device__ float         g_qkv [(size_t)MR*3*CC];      // 96MB
__device__ float         g_pos [(size_t)NHD*TT*TT];    // 64MB
__device__ float         g_x2  [(size_t)MR*CC];        // 32MB
__device__ __nv_bfloat16 g_act2[(size_t)MR*3*4096];    // 201MB split MLP hidden
__device__ __nv_bfloat16 g_wt  [(size_t)16*1024*1024]; // 32MB  split-transposed weights (reused)

// ============================================================
// helpers
// ============================================================
__device__ __forceinline__ uint32_t s2u(const void* p) {
    uint32_t a;
    asm("{ .reg .u64 t; cvta.to.shared.u64 t, %1; cvt.u32.u64 %0, t; }" : "=r"(a) : "l"(p));
    return a;
}
#define SWZ(x) ((x) ^ (((x) >> 3) & 0x70))

__device__ __forceinline__ void cpa16(uint32_t s, const void* g) {
    asm volatile("cp.async.cg.shared.global [%0], [%1], 16;" :: "r"(s), "l"(g));
}
#define CP_COMMIT() asm volatile("cp.async.commit_group;" ::: "memory")
#define CP_WAIT1()  asm volatile("cp.async.wait_group 1;" ::: "memory")

#define LDM_X4(r0, r1, r2, r3, a) \
    asm volatile("ldmatrix.sync.aligned.m8n8.x4.shared.b16 {%0,%1,%2,%3}, [%4];" \
        : "=r"(r0), "=r"(r1), "=r"(r2), "=r"(r3) : "r"(a))

#define MMA16816(d, a, b0v, b1v) \
    asm volatile("mma.sync.aligned.m16n8k16.row.col.f32.bf16.bf16.f32 " \
        "{%0,%1,%2,%3},{%4,%5,%6,%7},{%8,%9},{%0,%1,%2,%3};" \
        : "+f"((d)[0]), "+f"((d)[1]), "+f"((d)[2]), "+f"((d)[3]) \
        : "r"((a)[0]), "r"((a)[1]), "r"((a)[2]), "r"((a)[3]), "r"(b0v), "r"(b1v))

__device__ __forceinline__ float gelu_f(float v) {
    float c = 0.7978845608028654f;
    return 0.5f * v * (1.0f + tanhf(c * (v + 0.044715f * v * v * v)));
}
__device__ __forceinline__ void split2(float v, __nv_bfloat16& hi, __nv_bfloat16& lo) {
    hi = __float2bfloat16(v);
    lo = __float2bfloat16(v - __bfloat162float(hi));
}

// ============================================================
// LayerNorm -> split bf16 [hi(0:C) | lo(C:2C) | hi(2C:3C)]
// ============================================================
__global__ __launch_bounds__(256) void ln_split_kernel(
    const float* __restrict__ x, const float* __restrict__ g,
    const float* __restrict__ b, __nv_bfloat16* __restrict__ out)
{
    int row = blockIdx.x;
    int tid = threadIdx.x;
    float4 xv = reinterpret_cast<const float4*>(x + (size_t)row * CC)[tid];
    float s  = xv.x + xv.y + xv.z + xv.w;
    float sq = xv.x*xv.x + xv.y*xv.y + xv.z*xv.z + xv.w*xv.w;
#pragma unroll
    for (int o = 16; o > 0; o >>= 1) {
        s  += __shfl_xor_sync(0xffffffffu, s,  o);
        sq += __shfl_xor_sync(0xffffffffu, sq, o);
    }
    __shared__ float ss[8], ssq[8];
    int w = tid >> 5, l = tid & 31;
    if (l == 0) { ss[w] = s; ssq[w] = sq; }
    __syncthreads();
    if (tid == 0) {
        float a = 0.f, c = 0.f;
#pragma unroll
        for (int i = 0; i < 8; i++) { a += ss[i]; c += ssq[i]; }
        ss[0] = a; ssq[0] = c;
    }
    __syncthreads();
    float mu  = ss[0] * (1.0f / CC);
    float var = ssq[0] * (1.0f / CC) - mu * mu;
    float inv = rsqrtf(var + 1e-5f);
    float4 gv = reinterpret_cast<const float4*>(g)[tid];
    float4 bv = reinterpret_cast<const float4*>(b)[tid];
    float v[4];
    v[0] = (xv.x - mu) * inv * gv.x + bv.x;
    v[1] = (xv.y - mu) * inv * gv.y + bv.y;
    v[2] = (xv.z - mu) * inv * gv.z + bv.z;
    v[3] = (xv.w - mu) * inv * gv.w + bv.w;
    union { __nv_bfloat16 h[4]; uint2 q; } H, L;
#pragma unroll
    for (int i = 0; i < 4; i++) split2(v[i], H.h[i], L.h[i]);
    size_t rb = (size_t)row * (3 * CC) + tid * 4;
    *reinterpret_cast<uint2*>(out + rb)          = H.q;
    *reinterpret_cast<uint2*>(out + rb + CC)     = L.q;
    *reinterpret_cast<uint2*>(out + rb + 2 * CC) = H.q;
}

// ============================================================
// Weight transpose + split: W[K,N] fp32 -> WT[N, 3K] bf16 [hi | hi | lo]
// ============================================================
__global__ __launch_bounds__(256) void transpose_split_kernel(
    const float* __restrict__ W, __nv_bfloat16* __restrict__ WT, int K, int N)
{
    __shared__ float t[32][33];
    int tx = threadIdx.x & 31, ty = threadIdx.x >> 5;
    int n0 = blockIdx.x * 32, k0 = blockIdx.y * 32;
#pragma unroll
    for (int i = 0; i < 4; i++)
        t[ty + 8 * i][tx] = W[(size_t)(k0 + ty + 8 * i) * N + n0 + tx];
    __syncthreads();
    size_t Kp3 = 3 * (size_t)K;
#pragma unroll
    for (int i = 0; i < 4; i++) {
        int n = n0 + ty + 8 * i;
        int k = k0 + tx;
        float v = t[tx][ty + 8 * i];
        __nv_bfloat16 hi, lo;
        split2(v, hi, lo);
        WT[(size_t)n * Kp3 + k]         = hi;
        WT[(size_t)n * Kp3 + K + k]     = hi;
        WT[(size_t)n * Kp3 + 2 * K + k] = lo;
    }
}

// ============================================================
// mma.sync bf16 GEMM: C[M,N] = A[M,Kp] x WT[N,Kp], fp32 acc.
// BM=128 BN=128 BK=64, 3-stage cp.async, 256 threads, warp tile 64x32.
// EPI: 0 = +bias -> f32, 1 = gelu(+bias) -> split bf16 [hi|lo|hi], 2 = +bias+res -> f32
// ============================================================
template <int EPI>
__global__ __launch_bounds__(256) void mma_gemm(
    const __nv_bfloat16* __restrict__ A, const __nv_bfloat16* __restrict__ Bw,
    const float* __restrict__ bias, const float* __restrict__ res,
    void* __restrict__ Cout, int N, int Kp)
{
    constexpr int STAGE = 32768;       // 16KB A + 16KB B
    extern __shared__ char smem[];
    uint32_t sb = s2u(smem);

    int tid = threadIdx.x;
    int lane = tid & 31;
    int w = tid >> 5;
    int wm = w & 1;          // 2 warps in M
    int wn = w >> 1;         // 4 warps in N
    int bx = blockIdx.x, by = blockIdx.y;
    int nch = Kp >> 6;

    const __nv_bfloat16* Ag = A  + (size_t)(by * 128) * Kp;
    const __nv_bfloat16* Bg = Bw + (size_t)(bx * 128) * Kp;

    int lcol = (tid & 7) * 8;        // element col within 64

    auto load_stage = [&](int c, int s) {
        int k0 = c << 6;
        uint32_t sA = sb + s * STAGE;
        uint32_t sB = sA + 16384;
#pragma unroll
        for (int i = 0; i < 4; i++) {
            int u = tid + 256 * i;
            int row = u >> 3;
            cpa16(sA + SWZ((uint32_t)u * 16), Ag + (size_t)row * Kp + k0 + lcol);
            cpa16(sB + SWZ((uint32_t)u * 16), Bg + (size_t)row * Kp + k0 + lcol);
        }
        CP_COMMIT();
    };

    float acc[4][4][4];
#pragma unroll
    for (int i = 0; i < 4; i++)
#pragma unroll
        for (int j = 0; j < 4; j++)
#pragma unroll
            for (int q = 0; q < 4; q++) acc[i][j][q] = 0.f;

    load_stage(0, 0);
    load_stage(1, 1);

    for (int c = 0; c < nch; c++) {
        int s = c % 3;
        CP_WAIT1();
        __syncthreads();
        if (c + 2 < nch) load_stage(c + 2, (c + 2) % 3);
        else CP_COMMIT();   // keep group accounting uniform

        uint32_t sA = sb + s * STAGE;
        uint32_t sB = sA + 16384;
#pragma unroll
        for (int ks = 0; ks < 4; ks++) {
            int kb = ks * 32;  // bytes
            uint32_t a[4][4];
#pragma unroll
            for (int mt = 0; mt < 4; mt++) {
                int row = wm * 64 + mt * 16 + (lane & 15);
                uint32_t ad = sA + SWZ((uint32_t)(row * 128 + kb + ((lane >> 4) << 4)));
                LDM_X4(a[mt][0], a[mt][1], a[mt][2], a[mt][3], ad);
            }
            uint32_t bfr[4][2];
#pragma unroll
            for (int nt2 = 0; nt2 < 2; nt2++) {
                int nrow = wn * 32 + nt2 * 16 + ((lane >> 4) << 3) + (lane & 7);
                uint32_t ad = sB + SWZ((uint32_t)(nrow * 128 + kb + (((lane >> 3) & 1) << 4)));
                uint32_t r0, r1, r2, r3;
                LDM_X4(r0, r1, r2, r3, ad);
                bfr[nt2 * 2][0] = r0; bfr[nt2 * 2][1] = r1;
                bfr[nt2 * 2 + 1][0] = r2; bfr[nt2 * 2 + 1][1] = r3;
            }
#pragma unroll
            for (int mt = 0; mt < 4; mt++)
#pragma unroll
                for (int nt = 0; nt < 4; nt++)
                    MMA16816(acc[mt][nt], a[mt], bfr[nt][0], bfr[nt][1]);
        }
        __syncthreads();
    }

    // ---------- epilogue ----------
#pragma unroll
    for (int mt = 0; mt < 4; mt++) {
#pragma unroll
        for (int half = 0; half < 2; half++) {
            int r = by * 128 + wm * 64 + mt * 16 + (lane >> 2) + half * 8;
#pragma unroll
            for (int nt = 0; nt < 4; nt++) {
                int cc = bx * 128 + wn * 32 + nt * 8 + ((lane & 3) << 1);
                float v0 = acc[mt][nt][half * 2 + 0];
                float v1 = acc[mt][nt][half * 2 + 1];
                float2 bi = *reinterpret_cast<const float2*>(bias + cc);
                v0 += bi.x; v1 += bi.y;
                if (EPI == 2) {
                    float2 rv = *reinterpret_cast<const float2*>(res + (size_t)r * N + cc);
                    v0 += rv.x; v1 += rv.y;
                }
                if (EPI == 0 || EPI == 2) {
                    float2 o; o.x = v0; o.y = v1;
                    *reinterpret_cast<float2*>((float*)Cout + (size_t)r * N + cc) = o;
                } else {
                    v0 = gelu_f(v0); v1 = gelu_f(v1);
                    union { __nv_bfloat16 h[2]; uint32_t u; } H, L;
                    split2(v0, H.h[0], L.h[0]);
                    split2(v1, H.h[1], L.h[1]);
                    __nv_bfloat16* C = (__nv_bfloat16*)Cout;
                    size_t rbase = (size_t)r * (3 * (size_t)N) + cc;
                    *reinterpret_cast<uint32_t*>(C + rbase)               = H.u;
                    *reinterpret_cast<uint32_t*>(C + rbase + N)           = L.u;
                    *reinterpret_cast<uint32_t*>(C + rbase + 2 * (size_t)N) = H.u;
                }
            }
        }
    }
}

// ============================================================
// Positional bias projection
// ============================================================
__global__ __launch_bounds__(256) void posbias_kernel(
    const float* __restrict__ bias, const float* __restrict__ Wb,
    const float* __restrict__ bb, float* __restrict__ pos)
{
    __shared__ float w[16][17];
    __shared__ float bbs[16];
    int tid = threadIdx.x;
    w[tid >> 4][tid & 15] = Wb[tid];
    if (tid < 16) bbs[tid] = bb[tid];
    __syncthreads();
    int idx = blockIdx.x * 256 + tid;
    const float4* bp = reinterpret_cast<const float4*>(bias + (size_t)idx * 16);
    float4 b0 = bp[0], b1 = bp[1], b2 = bp[2], b3 = bp[3];
    float f[16] = { b0.x, b0.y, b0.z, b0.w, b1.x, b1.y, b1.z, b1.w,
                    b2.x, b2.y, b2.z, b2.w, b3.x, b3.y, b3.z, b3.w };
#pragma unroll
    for (int h = 0; h < 16; h++) {
        float acc = bbs[h];
#pragma unroll
        for (int ff = 0; ff < 16; ff++) acc += f[ff] * w[ff][h];
        pos[(size_t)h * TT * TT + idx] = acc;
    }
}

// ============================================================
// Flash-style attention (fp32); output written as split bf16 [hi|lo|hi]
// ============================================================
__global__ __launch_bounds__(256) void attn_kernel(
    const float* __restrict__ qkv, const float* __restrict__ pos,
    __nv_bfloat16* __restrict__ ysplit)
{
    extern __shared__ float sm[];
    float* qT = sm;
    float* kT = sm + 4096;
    float* vS = sm + 8192;
    float* sS = sm + 12288;
    float* mS = sm + 16384;
    float* lS = sm + 16448;
    float* scS = sm + 16512;

    int blk = blockIdx.x;
    int t0 = (blk & 15) << 6;
    int h  = (blk >> 4) & 15;
    int b  = blk >> 8;
    int tid = threadIdx.x;
    int tx = tid & 15, ty = tid >> 4;
    int tr = tid >> 2;
    int dc = (tid & 3) << 4;

    const float* qb = qkv + (size_t)(b * TT) * 3072 + h * 64;

#pragma unroll
    for (int l2 = 0; l2 < 4; l2++) {
        float4 v4 = *reinterpret_cast<const float4*>(qb + (size_t)(t0 + tr) * 3072 + dc + l2 * 4);
        int d = dc + l2 * 4;
        qT[(d + 0) * 64 + tr] = v4.x;
        qT[(d + 1) * 64 + tr] = v4.y;
        qT[(d + 2) * 64 + tr] = v4.z;
        qT[(d + 3) * 64 + tr] = v4.w;
    }
    if (tid < 64) { mS[tid] = -1e30f; lS[tid] = 0.f; }

    float o[4][4];
#pragma unroll
    for (int i = 0; i < 4; i++)
#pragma unroll
        for (int j = 0; j < 4; j++) o[i][j] = 0.f;

    const float* posb = pos + ((size_t)h * TT + t0) * TT;

    for (int s0 = 0; s0 < TT; s0 += 64) {
        const float* kb = qb + 1024 + (size_t)s0 * 3072;
        const float* vb = qb + 2048 + (size_t)s0 * 3072;
#pragma unroll
        for (int l2 = 0; l2 < 4; l2++) {
            int d = dc + l2 * 4;
            float4 k4 = *reinterpret_cast<const float4*>(kb + (size_t)tr * 3072 + d);
            kT[(d + 0) * 64 + tr] = k4.x;
            kT[(d + 1) * 64 + tr] = k4.y;
            kT[(d + 2) * 64 + tr] = k4.z;
            kT[(d + 3) * 64 + tr] = k4.w;
            float4 v4 = *reinterpret_cast<const float4*>(vb + (size_t)tr * 3072 + d);
            *reinterpret_cast<float4*>(&vS[tr * 64 + d]) = v4;
        }
        __syncthreads();

        float sa[4][4];
#pragma unroll
        for (int i = 0; i < 4; i++)
#pragma unroll
            for (int j = 0; j < 4; j++) sa[i][j] = 0.f;
#pragma unroll 8
        for (int d = 0; d < 64; d++) {
            float4 a4 = *reinterpret_cast<const float4*>(&qT[d * 64 + ty * 4]);
            float4 b4 = *reinterpret_cast<const float4*>(&kT[d * 64 + tx * 4]);
            float a[4] = { a4.x, a4.y, a4.z, a4.w };
            float bb2[4] = { b4.x, b4.y, b4.z, b4.w };
#pragma unroll
            for (int i = 0; i < 4; i++)
#pragma unroll
                for (int j = 0; j < 4; j++)
                    sa[i][j] += a[i] * bb2[j];
        }
#pragma unroll
        for (int i = 0; i < 4; i++) {
            int r = ty * 4 + i;
            float4 p4 = *reinterpret_cast<const float4*>(posb + (size_t)r * TT + s0 + tx * 4);
            sS[r * 64 + tx * 4 + 0] = sa[i][0] * 0.125f + p4.x;
            sS[r * 64 + tx * 4 + 1] = sa[i][1] * 0.125f + p4.y;
            sS[r * 64 + tx * 4 + 2] = sa[i][2] * 0.125f + p4.z;
            sS[r * 64 + tx * 4 + 3] = sa[i][3] * 0.125f + p4.w;
        }
        __syncthreads();

        {
            float vals[16];
            *reinterpret_cast<float4*>(vals)      = *reinterpret_cast<const float4*>(&sS[tr * 64 + dc]);
            *reinterpret_cast<float4*>(vals + 4)  = *reinterpret_cast<const float4*>(&sS[tr * 64 + dc + 4]);
            *reinterpret_cast<float4*>(vals + 8)  = *reinterpret_cast<const float4*>(&sS[tr * 64 + dc + 8]);
            *reinterpret_cast<float4*>(vals + 12) = *reinterpret_cast<const float4*>(&sS[tr * 64 + dc + 12]);
            float mx = vals[0];
#pragma unroll
            for (int q = 1; q < 16; q++) mx = fmaxf(mx, vals[q]);
            mx = fmaxf(mx, __shfl_xor_sync(0xffffffffu, mx, 1));
            mx = fmaxf(mx, __shfl_xor_sync(0xffffffffu, mx, 2));
            float m_old = mS[tr];
            float m_new = fmaxf(m_old, mx);
            float sum = 0.f;
#pragma unroll
            for (int q = 0; q < 16; q++) { vals[q] = __expf(vals[q] - m_new); sum += vals[q]; }
            *reinterpret_cast<float4*>(&sS[tr * 64 + dc])      = *reinterpret_cast<float4*>(vals);
            *reinterpret_cast<float4*>(&sS[tr * 64 + dc + 4])  = *reinterpret_cast<float4*>(vals + 4);
            *reinterpret_cast<float4*>(&sS[tr * 64 + dc + 8])  = *reinterpret_cast<float4*>(vals + 8);
            *reinterpret_cast<float4*>(&sS[tr * 64 + dc + 12]) = *reinterpret_cast<float4*>(vals + 12);
            sum += __shfl_xor_sync(0xffffffffu, sum, 1);
            sum += __shfl_xor_sync(0xffffffffu, sum, 2);
            if ((tid & 3) == 0) {
                float sc = __expf(m_old - m_new);
                scS[tr] = sc;
                lS[tr] = lS[tr] * sc + sum;
                mS[tr] = m_new;
            }
        }
        __syncthreads();

#pragma unroll
        for (int i = 0; i < 4; i++) {
            float sc = scS[ty * 4 + i];
            o[i][0] *= sc; o[i][1] *= sc; o[i][2] *= sc; o[i][3] *= sc;
        }
#pragma unroll 4
        for (int s = 0; s < 64; s++) {
            float4 v4 = *reinterpret_cast<const float4*>(&vS[s * 64 + tx * 4]);
#pragma unroll
            for (int i = 0; i < 4; i++) {
                float p = sS[(ty * 4 + i) * 64 + s];
                o[i][0] += p * v4.x;
                o[i][1] += p * v4.y;
                o[i][2] += p * v4.z;
                o[i][3] += p * v4.w;
            }
        }
        __syncthreads();
    }

#pragma unroll
    for (int i = 0; i < 4; i++) {
        int r = ty * 4 + i;
        float inv = 1.0f / lS[r];
        float v[4] = { o[i][0] * inv, o[i][1] * inv, o[i][2] * inv, o[i][3] * inv };
        union { __nv_bfloat16 h[4]; uint2 q; } H, L;
#pragma unroll
        for (int j = 0; j < 4; j++) split2(v[j], H.h[j], L.h[j]);
        size_t rb = (size_t)(b * TT + t0 + r) * (3 * CC) + h * 64 + tx * 4;
        *reinterpret_cast<uint2*>(ysplit + rb)          = H.q;
        *reinterpret_cast<uint2*>(ysplit + rb + CC)     = L.q;
        *reinterpret_cast<uint2*>(ysplit + rb + 2 * CC) = H.q;
    }
}

// ============================================================
extern "C" void kernel_launch(void* const* d_in, const int* in_sizes, int n_in,
                              void* d_out, int out_size)
{
    const float* x      = (const float*)d_in[0];
    const float* bias   = (const float*)d_in[1];
    const float* ln1_g  = (const float*)d_in[2];
    const float* ln1_b  = (const float*)d_in[3];
    const float* W_attn = (const float*)d_in[4];
    const float* b_attn = (const float*)d_in[5];
    const float* W_o    = (const float*)d_in[6];
    const float* b_o    = (const float*)d_in[7];
    const float* W_bias = (const float*)d_in[8];
    const float* b_bias = (const float*)d_in[9];
    const float* ln2_g  = (const float*)d_in[10];
    const float* ln2_b  = (const float*)d_in[11];
    const float* W_fc   = (const float*)d_in[12];
    const float* b_fc   = (const float*)d_in[13];
    const float* W_fc2  = (const float*)d_in[14];
    const float* b_fc2  = (const float*)d_in[15];
    float* out = (float*)d_out;

    __nv_bfloat16 *psa, *pact2, *pwt;
    float *pqkv, *ppos, *px2;
    cudaGetSymbolAddress((void**)&psa,   g_sa);
    cudaGetSymbolAddress((void**)&pqkv,  g_qkv);
    cudaGetSymbolAddress((void**)&ppos,  g_pos);
    cudaGetSymbolAddress((void**)&px2,   g_x2);
    cudaGetSymbolAddress((void**)&pact2, g_act2);
    cudaGetSymbolAddress((void**)&pwt,   g_wt);

    const int GSMEM = 3 * 32768;  // 96KB
    cudaFuncSetAttribute(mma_gemm<0>, cudaFuncAttributeMaxDynamicSharedMemorySize, GSMEM);
    cudaFuncSetAttribute(mma_gemm<1>, cudaFuncAttributeMaxDynamicSharedMemorySize, GSMEM);
    cudaFuncSetAttribute(mma_gemm<2>, cudaFuncAttributeMaxDynamicSharedMemorySize, GSMEM);
    cudaFuncSetAttribute(attn_kernel, cudaFuncAttributeMaxDynamicSharedMemorySize, 66304);

    // 1) LN1 -> split
    ln_split_kernel<<<MR, 256>>>(x, ln1_g, ln1_b, psa);
    // 2) QKV = h @ W_attn + b_attn
    transpose_split_kernel<<<dim3(3072/32, 1024/32), 256>>>(W_attn, pwt, 1024, 3072);
    mma_gemm<0><<<dim3(3072/128, MR/128), 256, GSMEM>>>(psa, pwt, b_attn, nullptr, pqkv, 3072, 3072);
    // 3) positional bias projection
    posbias_kernel<<<(TT * TT) / 256, 256>>>(bias, W_bias, b_bias, ppos);
    // 4) attention -> split y
    attn_kernel<<<BB * NHD * (TT / 64), 256, 66304>>>(pqkv, ppos, psa);
    // 5) x2 = x + y @ W_o + b_o
    transpose_split_kernel<<<dim3(1024/32, 1024/32), 256>>>(W_o, pwt, 1024, 1024);
    mma_gemm<2><<<dim3(1024/128, MR/128), 256, GSMEM>>>(psa, pwt, b_o, x, px2, 1024, 3072);
    // 6) LN2 -> split
    ln_split_kernel<<<MR, 256>>>(px2, ln2_g, ln2_b, psa);
    // 7) act = gelu(h2 @ W_fc + b_fc) -> split
    transpose_split_kernel<<<dim3(4096/32, 1024/32), 256>>>(W_fc, pwt, 1024, 4096);
    mma_gemm<1><<<dim3(4096/128, MR/128), 256, GSMEM>>>(psa, pwt, b_fc, nullptr, pact2, 4096, 3072);
    // 8) out = x2 + act @ W_fc2 + b_fc2
    transpose_split_kernel<<<dim3(1024/32, 4096/32), 256>>>(W_fc2, pwt, 4096, 1024);
    mma_gemm<2><<<dim3(1024/128, MR/128), 256, GSMEM>>>(pact2, pwt, b_fc2, px2, out, 1024, 12288);
}

// round 5
// speedup vs baseline: 2.1333x; 1.2474x over previous
#include <cuda_runtime.h>
#include <cuda_bf16.h>
#include <math.h>
#include <stdint.h>

#define TT 1024
#define BB 8
#define CC 1024
#define NHD 16
#define MR (BB*TT)   // 8192 tokens

// ---- static scratch (no allocations allowed) ----
__device__ __nv_bfloat16 g_sa  [(size_t)MR*3*CC];      // split activations [hi|lo|hi]
__device__ __nv_bfloat16 g_qkv2[(size_t)3*BB*NHD*TT*128]; // q/k/v split planes [b][h][t][hi64|lo64]
__device__ float         g_pos [(size_t)NHD*TT*TT];    // [h][t][s]
__device__ float         g_x2  [(size_t)MR*CC];
__device__ __nv_bfloat16 g_act2[(size_t)MR*3*4096];    // split MLP hidden
__device__ __nv_bfloat16 g_wt  [(size_t)16*1024*1024]; // split-transposed weights (reused)

#define QKV_PLANE ((size_t)BB*NHD*TT*128)   // 16,777,216 elements per q/k/v

// ============================================================
// helpers
// ============================================================
__device__ __forceinline__ uint32_t s2u(const void* p) {
    uint32_t a;
    asm("{ .reg .u64 t; cvta.to.shared.u64 t, %1; cvt.u32.u64 %0, t; }" : "=r"(a) : "l"(p));
    return a;
}
#define SWZ(x) ((x) ^ (((x) >> 3) & 0x70))

__device__ __forceinline__ void cpa16(uint32_t s, const void* g) {
    asm volatile("cp.async.cg.shared.global [%0], [%1], 16;" :: "r"(s), "l"(g));
}
#define CP_COMMIT() asm volatile("cp.async.commit_group;" ::: "memory")
#define CP_WAIT0()  asm volatile("cp.async.wait_group 0;" ::: "memory")
#define CP_WAIT1()  asm volatile("cp.async.wait_group 1;" ::: "memory")

#define LDM_X4(r0, r1, r2, r3, a) \
    asm volatile("ldmatrix.sync.aligned.m8n8.x4.shared.b16 {%0,%1,%2,%3}, [%4];" \
        : "=r"(r0), "=r"(r1), "=r"(r2), "=r"(r3) : "r"(a))

#define LDM_X4_T(r0, r1, r2, r3, a) \
    asm volatile("ldmatrix.sync.aligned.m8n8.x4.trans.shared.b16 {%0,%1,%2,%3}, [%4];" \
        : "=r"(r0), "=r"(r1), "=r"(r2), "=r"(r3) : "r"(a))

#define MMA16816(d, a, b0v, b1v) \
    asm volatile("mma.sync.aligned.m16n8k16.row.col.f32.bf16.bf16.f32 " \
        "{%0,%1,%2,%3},{%4,%5,%6,%7},{%8,%9},{%0,%1,%2,%3};" \
        : "+f"((d)[0]), "+f"((d)[1]), "+f"((d)[2]), "+f"((d)[3]) \
        : "r"((a)[0]), "r"((a)[1]), "r"((a)[2]), "r"((a)[3]), "r"(b0v), "r"(b1v))

__device__ __forceinline__ float gelu_f(float v) {
    float c = 0.7978845608028654f;
    return 0.5f * v * (1.0f + tanhf(c * (v + 0.044715f * v * v * v)));
}
__device__ __forceinline__ void split2(float v, __nv_bfloat16& hi, __nv_bfloat16& lo) {
    hi = __float2bfloat16(v);
    lo = __float2bfloat16(v - __bfloat162float(hi));
}
__device__ __forceinline__ uint32_t pack_split_hi(float v0, float v1, uint32_t& loOut) {
    union { __nv_bfloat16 h[2]; uint32_t u; } H, L;
    split2(v0, H.h[0], L.h[0]);
    split2(v1, H.h[1], L.h[1]);
    loOut = L.u;
    return H.u;
}

// ============================================================
// LayerNorm -> split bf16 [hi(0:C) | lo(C:2C) | hi(2C:3C)]
// ============================================================
__global__ __launch_bounds__(256) void ln_split_kernel(
    const float* __restrict__ x, const float* __restrict__ g,
    const float* __restrict__ b, __nv_bfloat16* __restrict__ out)
{
    int row = blockIdx.x;
    int tid = threadIdx.x;
    float4 xv = reinterpret_cast<const float4*>(x + (size_t)row * CC)[tid];
    float s  = xv.x + xv.y + xv.z + xv.w;
    float sq = xv.x*xv.x + xv.y*xv.y + xv.z*xv.z + xv.w*xv.w;
#pragma unroll
    for (int o = 16; o > 0; o >>= 1) {
        s  += __shfl_xor_sync(0xffffffffu, s,  o);
        sq += __shfl_xor_sync(0xffffffffu, sq, o);
    }
    __shared__ float ss[8], ssq[8];
    int w = tid >> 5, l = tid & 31;
    if (l == 0) { ss[w] = s; ssq[w] = sq; }
    __syncthreads();
    if (tid == 0) {
        float a = 0.f, c = 0.f;
#pragma unroll
        for (int i = 0; i < 8; i++) { a += ss[i]; c += ssq[i]; }
        ss[0] = a; ssq[0] = c;
    }
    __syncthreads();
    float mu  = ss[0] * (1.0f / CC);
    float var = ssq[0] * (1.0f / CC) - mu * mu;
    float inv = rsqrtf(var + 1e-5f);
    float4 gv = reinterpret_cast<const float4*>(g)[tid];
    float4 bv = reinterpret_cast<const float4*>(b)[tid];
    float v[4];
    v[0] = (xv.x - mu) * inv * gv.x + bv.x;
    v[1] = (xv.y - mu) * inv * gv.y + bv.y;
    v[2] = (xv.z - mu) * inv * gv.z + bv.z;
    v[3] = (xv.w - mu) * inv * gv.w + bv.w;
    union { __nv_bfloat16 h[4]; uint2 q; } H, L;
#pragma unroll
    for (int i = 0; i < 4; i++) split2(v[i], H.h[i], L.h[i]);
    size_t rb = (size_t)row * (3 * CC) + tid * 4;
    *reinterpret_cast<uint2*>(out + rb)          = H.q;
    *reinterpret_cast<uint2*>(out + rb + CC)     = L.q;
    *reinterpret_cast<uint2*>(out + rb + 2 * CC) = H.q;
}

// ============================================================
// Weight transpose + split: W[K,N] fp32 -> WT[N, 3K] bf16 [hi | hi | lo]
// ============================================================
__global__ __launch_bounds__(256) void transpose_split_kernel(
    const float* __restrict__ W, __nv_bfloat16* __restrict__ WT, int K, int N)
{
    __shared__ float t[32][33];
    int tx = threadIdx.x & 31, ty = threadIdx.x >> 5;
    int n0 = blockIdx.x * 32, k0 = blockIdx.y * 32;
#pragma unroll
    for (int i = 0; i < 4; i++)
        t[ty + 8 * i][tx] = W[(size_t)(k0 + ty + 8 * i) * N + n0 + tx];
    __syncthreads();
    size_t Kp3 = 3 * (size_t)K;
#pragma unroll
    for (int i = 0; i < 4; i++) {
        int n = n0 + ty + 8 * i;
        int k = k0 + tx;
        float v = t[tx][ty + 8 * i];
        __nv_bfloat16 hi, lo;
        split2(v, hi, lo);
        WT[(size_t)n * Kp3 + k]         = hi;
        WT[(size_t)n * Kp3 + K + k]     = hi;
        WT[(size_t)n * Kp3 + 2 * K + k] = lo;
    }
}

// ============================================================
// mma.sync bf16 GEMM. EPI: 1 = gelu(+bias) -> split bf16 [hi|lo|hi],
// 2 = +bias+res -> f32, 3 = +bias -> qkv split planes [b][h][t][hi|lo]
// ============================================================
template <int EPI>
__global__ __launch_bounds__(256) void mma_gemm(
    const __nv_bfloat16* __restrict__ A, const __nv_bfloat16* __restrict__ Bw,
    const float* __restrict__ bias, const float* __restrict__ res,
    void* __restrict__ Cout, int N, int Kp)
{
    constexpr int STAGE = 32768;       // 16KB A + 16KB B
    extern __shared__ char smem[];
    uint32_t sb = s2u(smem);

    int tid = threadIdx.x;
    int lane = tid & 31;
    int w = tid >> 5;
    int wm = w & 1;
    int wn = w >> 1;
    int bx = blockIdx.x, by = blockIdx.y;
    int nch = Kp >> 6;

    const __nv_bfloat16* Ag = A  + (size_t)(by * 128) * Kp;
    const __nv_bfloat16* Bg = Bw + (size_t)(bx * 128) * Kp;

    int lcol = (tid & 7) * 8;

    auto load_stage = [&](int c, int s) {
        int k0 = c << 6;
        uint32_t sA = sb + s * STAGE;
        uint32_t sB = sA + 16384;
#pragma unroll
        for (int i = 0; i < 4; i++) {
            int u = tid + 256 * i;
            int row = u >> 3;
            cpa16(sA + SWZ((uint32_t)u * 16), Ag + (size_t)row * Kp + k0 + lcol);
            cpa16(sB + SWZ((uint32_t)u * 16), Bg + (size_t)row * Kp + k0 + lcol);
        }
        CP_COMMIT();
    };

    float acc[4][4][4];
#pragma unroll
    for (int i = 0; i < 4; i++)
#pragma unroll
        for (int j = 0; j < 4; j++)
#pragma unroll
            for (int q = 0; q < 4; q++) acc[i][j][q] = 0.f;

    load_stage(0, 0);
    load_stage(1, 1);

    for (int c = 0; c < nch; c++) {
        int s = c % 3;
        CP_WAIT1();
        __syncthreads();
        if (c + 2 < nch) load_stage(c + 2, (c + 2) % 3);
        else CP_COMMIT();

        uint32_t sA = sb + s * STAGE;
        uint32_t sB = sA + 16384;
#pragma unroll
        for (int ks = 0; ks < 4; ks++) {
            int kb = ks * 32;
            uint32_t a[4][4];
#pragma unroll
            for (int mt = 0; mt < 4; mt++) {
                int row = wm * 64 + mt * 16 + (lane & 15);
                uint32_t ad = sA + SWZ((uint32_t)(row * 128 + kb + ((lane >> 4) << 4)));
                LDM_X4(a[mt][0], a[mt][1], a[mt][2], a[mt][3], ad);
            }
            uint32_t bfr[4][2];
#pragma unroll
            for (int nt2 = 0; nt2 < 2; nt2++) {
                int nrow = wn * 32 + nt2 * 16 + ((lane >> 4) << 3) + (lane & 7);
                uint32_t ad = sB + SWZ((uint32_t)(nrow * 128 + kb + (((lane >> 3) & 1) << 4)));
                uint32_t r0, r1, r2, r3;
                LDM_X4(r0, r1, r2, r3, ad);
                bfr[nt2 * 2][0] = r0; bfr[nt2 * 2][1] = r1;
                bfr[nt2 * 2 + 1][0] = r2; bfr[nt2 * 2 + 1][1] = r3;
            }
#pragma unroll
            for (int mt = 0; mt < 4; mt++)
#pragma unroll
                for (int nt = 0; nt < 4; nt++)
                    MMA16816(acc[mt][nt], a[mt], bfr[nt][0], bfr[nt][1]);
        }
        __syncthreads();
    }

    // ---------- epilogue ----------
#pragma unroll
    for (int mt = 0; mt < 4; mt++) {
#pragma unroll
        for (int half = 0; half < 2; half++) {
            int r = by * 128 + wm * 64 + mt * 16 + (lane >> 2) + half * 8;
#pragma unroll
            for (int nt = 0; nt < 4; nt++) {
                int cc = bx * 128 + wn * 32 + nt * 8 + ((lane & 3) << 1);
                float v0 = acc[mt][nt][half * 2 + 0];
                float v1 = acc[mt][nt][half * 2 + 1];
                float2 bi = *reinterpret_cast<const float2*>(bias + cc);
                v0 += bi.x; v1 += bi.y;
                if (EPI == 2) {
                    float2 rv = *reinterpret_cast<const float2*>(res + (size_t)r * N + cc);
                    v0 += rv.x; v1 += rv.y;
                    float2 o; o.x = v0; o.y = v1;
                    *reinterpret_cast<float2*>((float*)Cout + (size_t)r * N + cc) = o;
                } else if (EPI == 1) {
                    v0 = gelu_f(v0); v1 = gelu_f(v1);
                    uint32_t lo, hi = pack_split_hi(v0, v1, lo);
                    __nv_bfloat16* C = (__nv_bfloat16*)Cout;
                    size_t rbase = (size_t)r * (3 * (size_t)N) + cc;
                    *reinterpret_cast<uint32_t*>(C + rbase)                  = hi;
                    *reinterpret_cast<uint32_t*>(C + rbase + N)              = lo;
                    *reinterpret_cast<uint32_t*>(C + rbase + 2 * (size_t)N)  = hi;
                } else { // EPI == 3: qkv split planes
                    int kind = cc >> 10;           // 0=q,1=k,2=v
                    int hh   = (cc & 1023) >> 6;
                    int d    = cc & 63;
                    int bI   = r >> 10;
                    int t    = r & 1023;
                    uint32_t lo, hi = pack_split_hi(v0, v1, lo);
                    __nv_bfloat16* C = (__nv_bfloat16*)Cout + (size_t)kind * QKV_PLANE;
                    size_t base = ((((size_t)bI * NHD + hh) << 10) + t) * 128;
                    *reinterpret_cast<uint32_t*>(C + base + d)      = hi;
                    *reinterpret_cast<uint32_t*>(C + base + 64 + d) = lo;
                }
            }
        }
    }
}

// ============================================================
// Positional bias projection
// ============================================================
__global__ __launch_bounds__(256) void posbias_kernel(
    const float* __restrict__ bias, const float* __restrict__ Wb,
    const float* __restrict__ bb, float* __restrict__ pos)
{
    __shared__ float w[16][17];
    __shared__ float bbs[16];
    int tid = threadIdx.x;
    w[tid >> 4][tid & 15] = Wb[tid];
    if (tid < 16) bbs[tid] = bb[tid];
    __syncthreads();
    int idx = blockIdx.x * 256 + tid;
    const float4* bp = reinterpret_cast<const float4*>(bias + (size_t)idx * 16);
    float4 b0 = bp[0], b1 = bp[1], b2 = bp[2], b3 = bp[3];
    float f[16] = { b0.x, b0.y, b0.z, b0.w, b1.x, b1.y, b1.z, b1.w,
                    b2.x, b2.y, b2.z, b2.w, b3.x, b3.y, b3.z, b3.w };
#pragma unroll
    for (int h = 0; h < 16; h++) {
        float acc = bbs[h];
#pragma unroll
        for (int ff = 0; ff < 16; ff++) acc += f[ff] * w[ff][h];
        pos[(size_t)h * TT * TT + idx] = acc;
    }
}

// ============================================================
// Tensor-core flash attention (split-bf16, fp32 softmax)
// block = (b, h, t-tile 64), 256 threads = 8 warps (4 in M x 2 in N)
// ============================================================
// smem offsets (bytes)
#define SM_QHI   0
#define SM_QLO   8192
#define SM_K     16384        // 2 bufs x (hi 8K + lo 8K)
#define SM_VHI   49152
#define SM_VLO   57344
#define SM_PHI   65536
#define SM_PLO   73728
#define SM_POS   81920        // 64 rows x 272B (68-float pitch)
#define SM_MS    99328
#define SM_LS    99584
#define SM_SC    99840
#define SM_PM    100096       // [64][2] f32
#define SM_PL    100608       // [64][2] f32
#define SM_ATTN_TOTAL 101376

__global__ __launch_bounds__(256) void attn_tc_kernel(
    const __nv_bfloat16* __restrict__ qkv2, const float* __restrict__ pos,
    __nv_bfloat16* __restrict__ ysplit)
{
    extern __shared__ char smem[];
    uint32_t sb = s2u(smem);

    int blk = blockIdx.x;
    int t0 = (blk & 15) << 6;
    int h  = (blk >> 4) & 15;
    int b  = blk >> 8;
    int tid = threadIdx.x;
    int lane = tid & 31;
    int w = tid >> 5;
    int wm = w & 3;            // 4 warps over M(t)
    int wn = w >> 2;           // 2 warps over N
    int r0l = wm * 16 + (lane >> 2);   // local row 0 (0..63)
    int r1l = r0l + 8;

    const __nv_bfloat16* qg = qkv2 + ((((size_t)b * NHD + h) << 10) + t0) * 128;
    const __nv_bfloat16* kg = qkv2 + QKV_PLANE     + (((size_t)b * NHD + h) << 10) * 128;
    const __nv_bfloat16* vg = qkv2 + 2 * QKV_PLANE + (((size_t)b * NHD + h) << 10) * 128;
    const float* posg = pos + ((size_t)h * TT + t0) * TT;

    float* mS  = reinterpret_cast<float*>(smem + SM_MS);
    float* lS  = reinterpret_cast<float*>(smem + SM_LS);
    float* scS = reinterpret_cast<float*>(smem + SM_SC);
    float* pm  = reinterpret_cast<float*>(smem + SM_PM);
    float* pl  = reinterpret_cast<float*>(smem + SM_PL);
    float* posf = reinterpret_cast<float*>(smem + SM_POS);

    // split-plane loader: src rows of 128 elems = [hi64|lo64]
    auto load_split = [&](uint32_t dhi, uint32_t dlo, const __nv_bfloat16* src) {
#pragma unroll
        for (int it = 0; it < 2; it++) {
            int u = tid + it * 256;
            int r = u >> 3, c = u & 7;
            cpa16(dhi + SWZ((uint32_t)u * 16), src + (size_t)r * 128 + c * 8);
            cpa16(dlo + SWZ((uint32_t)u * 16), src + (size_t)r * 128 + 64 + c * 8);
        }
    };

    // prologue: Q + K0
    load_split(sb + SM_QHI, sb + SM_QLO, qg);
    load_split(sb + SM_K, sb + SM_K + 8192, kg);
    CP_COMMIT();
    if (tid < 64) { mS[tid] = -1e30f; lS[tid] = 0.f; }
    CP_WAIT0();
    __syncthreads();

    float oacc[4][4];
#pragma unroll
    for (int i = 0; i < 4; i++)
#pragma unroll
        for (int j = 0; j < 4; j++) oacc[i][j] = 0.f;

    // cache Q-hi A fragments (reused every tile, segs 0 & 2)
    uint32_t aH[4][4], aL[4][4];
#pragma unroll
    for (int kk = 0; kk < 4; kk++) {
        int row = wm * 16 + (lane & 15);
        uint32_t adr = sb + SM_QHI + SWZ((uint32_t)(row * 128 + kk * 32 + ((lane >> 4) << 4)));
        LDM_X4(aH[kk][0], aH[kk][1], aH[kk][2], aH[kk][3], adr);
        adr = sb + SM_QLO + SWZ((uint32_t)(row * 128 + kk * 32 + ((lane >> 4) << 4)));
        LDM_X4(aL[kk][0], aL[kk][1], aL[kk][2], aL[kk][3], adr);
    }

    for (int i = 0; i < 16; i++) {
        int buf = i & 1;
        // group A: pos_i + V_i
#pragma unroll
        for (int it = 0; it < 4; it++) {
            int u = tid + it * 256;
            int rr = u >> 4, c = u & 15;
            cpa16(sb + SM_POS + rr * 272 + c * 16, posg + (size_t)rr * TT + i * 64 + c * 4);
        }
        load_split(sb + SM_VHI, sb + SM_VLO, vg + (size_t)(i * 64) * 128);
        CP_COMMIT();
        // group B: K_{i+1}
        bool haveB = (i < 15);
        if (haveB) {
            uint32_t kd = sb + SM_K + (buf ^ 1) * 16384;
            load_split(kd, kd + 8192, kg + (size_t)((i + 1) * 64) * 128);
            CP_COMMIT();
        }

        // ---- S = Q K^T (3-term split) ----
        uint32_t khi = sb + SM_K + buf * 16384;
        uint32_t klo = khi + 8192;
        float sacc[4][4];
#pragma unroll
        for (int x1 = 0; x1 < 4; x1++)
#pragma unroll
            for (int x2 = 0; x2 < 4; x2++) sacc[x1][x2] = 0.f;
#pragma unroll
        for (int seg = 0; seg < 3; seg++) {
            uint32_t kpl = (seg == 2) ? klo : khi;
#pragma unroll
            for (int kk = 0; kk < 4; kk++) {
                uint32_t* a = (seg == 1) ? aL[kk] : aH[kk];
#pragma unroll
                for (int nt2 = 0; nt2 < 2; nt2++) {
                    int nrow = wn * 32 + nt2 * 16 + ((lane >> 4) << 3) + (lane & 7);
                    uint32_t bd = kpl + SWZ((uint32_t)(nrow * 128 + kk * 32 + (((lane >> 3) & 1) << 4)));
                    uint32_t br0, br1, br2, br3;
                    LDM_X4(br0, br1, br2, br3, bd);
                    MMA16816(sacc[nt2 * 2],     a, br0, br1);
                    MMA16816(sacc[nt2 * 2 + 1], a, br2, br3);
                }
            }
        }

        CP_WAIT1();            // group A (pos, V) done; group B may pend
        __syncthreads();

        // ---- softmax ----
        // add pos, scale; row-max partials
        float mx0 = -1e30f, mx1 = -1e30f;
#pragma unroll
        for (int nt = 0; nt < 4; nt++) {
            int colb = wn * 32 + nt * 8 + ((lane & 3) << 1);
            sacc[nt][0] = sacc[nt][0] * 0.125f + posf[r0l * 68 + colb];
            sacc[nt][1] = sacc[nt][1] * 0.125f + posf[r0l * 68 + colb + 1];
            sacc[nt][2] = sacc[nt][2] * 0.125f + posf[r1l * 68 + colb];
            sacc[nt][3] = sacc[nt][3] * 0.125f + posf[r1l * 68 + colb + 1];
            mx0 = fmaxf(mx0, fmaxf(sacc[nt][0], sacc[nt][1]));
            mx1 = fmaxf(mx1, fmaxf(sacc[nt][2], sacc[nt][3]));
        }
        mx0 = fmaxf(mx0, __shfl_xor_sync(0xffffffffu, mx0, 1));
        mx0 = fmaxf(mx0, __shfl_xor_sync(0xffffffffu, mx0, 2));
        mx1 = fmaxf(mx1, __shfl_xor_sync(0xffffffffu, mx1, 1));
        mx1 = fmaxf(mx1, __shfl_xor_sync(0xffffffffu, mx1, 2));
        if ((lane & 3) == 0) { pm[r0l * 2 + wn] = mx0; pm[r1l * 2 + wn] = mx1; }
        __syncthreads();
        if (tid < 64) {
            float m_old = mS[tid];
            float m_new = fmaxf(m_old, fmaxf(pm[tid * 2], pm[tid * 2 + 1]));
            scS[tid] = __expf(m_old - m_new);
            mS[tid] = m_new;
        }
        __syncthreads();
        float mn0 = mS[r0l], mn1 = mS[r1l];
        float sc0 = scS[r0l], sc1 = scS[r1l];
        float sum0 = 0.f, sum1 = 0.f;
#pragma unroll
        for (int nt = 0; nt < 4; nt++) {
            int colb = wn * 32 + nt * 8 + ((lane & 3) << 1);
            float p0 = __expf(sacc[nt][0] - mn0);
            float p1 = __expf(sacc[nt][1] - mn0);
            float p2 = __expf(sacc[nt][2] - mn1);
            float p3 = __expf(sacc[nt][3] - mn1);
            sum0 += p0 + p1; sum1 += p2 + p3;
            uint32_t lo, hi;
            hi = pack_split_hi(p0, p1, lo);
            *reinterpret_cast<uint32_t*>(smem + SM_PHI + SWZ((uint32_t)(r0l * 128 + colb * 2))) = hi;
            *reinterpret_cast<uint32_t*>(smem + SM_PLO + SWZ((uint32_t)(r0l * 128 + colb * 2))) = lo;
            hi = pack_split_hi(p2, p3, lo);
            *reinterpret_cast<uint32_t*>(smem + SM_PHI + SWZ((uint32_t)(r1l * 128 + colb * 2))) = hi;
            *reinterpret_cast<uint32_t*>(smem + SM_PLO + SWZ((uint32_t)(r1l * 128 + colb * 2))) = lo;
            // rescale O
            oacc[nt][0] *= sc0; oacc[nt][1] *= sc0;
            oacc[nt][2] *= sc1; oacc[nt][3] *= sc1;
        }
        sum0 += __shfl_xor_sync(0xffffffffu, sum0, 1);
        sum0 += __shfl_xor_sync(0xffffffffu, sum0, 2);
        sum1 += __shfl_xor_sync(0xffffffffu, sum1, 1);
        sum1 += __shfl_xor_sync(0xffffffffu, sum1, 2);
        if ((lane & 3) == 0) { pl[r0l * 2 + wn] = sum0; pl[r1l * 2 + wn] = sum1; }
        __syncthreads();
        if (tid < 64)
            lS[tid] = lS[tid] * scS[tid] + pl[tid * 2] + pl[tid * 2 + 1];

        // ---- O += P V (3-term split), V fragments via ldmatrix.trans ----
#pragma unroll
        for (int seg = 0; seg < 3; seg++) {
            uint32_t ppl = sb + ((seg == 1) ? SM_PLO : SM_PHI);
            uint32_t vpl = sb + ((seg == 2) ? SM_VLO : SM_VHI);
#pragma unroll
            for (int kk = 0; kk < 4; kk++) {
                uint32_t a[4];
                {
                    int row = wm * 16 + (lane & 15);
                    uint32_t adr = ppl + SWZ((uint32_t)(row * 128 + kk * 32 + ((lane >> 4) << 4)));
                    LDM_X4(a[0], a[1], a[2], a[3], adr);
                }
#pragma unroll
                for (int p = 0; p < 2; p++) {
                    int g2 = lane >> 3, gi = lane & 7;
                    int row = kk * 16 + (g2 & 1) * 8 + gi;
                    int colb = (wn * 32 + p * 16 + (g2 >> 1) * 8) * 2;
                    uint32_t adr = vpl + SWZ((uint32_t)(row * 128 + colb));
                    uint32_t br0, br1, br2, br3;
                    LDM_X4_T(br0, br1, br2, br3, adr);
                    MMA16816(oacc[p * 2],     a, br0, br1);
                    MMA16816(oacc[p * 2 + 1], a, br2, br3);
                }
            }
        }
        CP_WAIT0();            // K_{i+1} ready
        __syncthreads();       // V/pos/P buffers reusable
    }

    // ---- epilogue: normalize, write split y ----
    float inv0 = 1.0f / lS[r0l];
    float inv1 = 1.0f / lS[r1l];
    size_t rb0 = ((size_t)(b * TT + t0 + r0l)) * (3 * CC) + h * 64;
    size_t rb1 = ((size_t)(b * TT + t0 + r1l)) * (3 * CC) + h * 64;
#pragma unroll
    for (int nt = 0; nt < 4; nt++) {
        int d = wn * 32 + nt * 8 + ((lane & 3) << 1);
        uint32_t lo, hi;
        hi = pack_split_hi(oacc[nt][0] * inv0, oacc[nt][1] * inv0, lo);
        *reinterpret_cast<uint32_t*>(ysplit + rb0 + d)          = hi;
        *reinterpret_cast<uint32_t*>(ysplit + rb0 + CC + d)     = lo;
        *reinterpret_cast<uint32_t*>(ysplit + rb0 + 2 * CC + d) = hi;
        hi = pack_split_hi(oacc[nt][2] * inv1, oacc[nt][3] * inv1, lo);
        *reinterpret_cast<uint32_t*>(ysplit + rb1 + d)          = hi;
        *reinterpret_cast<uint32_t*>(ysplit + rb1 + CC + d)     = lo;
        *reinterpret_cast<uint32_t*>(ysplit + rb1 + 2 * CC + d) = hi;
    }
}

// ============================================================
extern "C" void kernel_launch(void* const* d_in, const int* in_sizes, int n_in,
                              void* d_out, int out_size)
{
    const float* x      = (const float*)d_in[0];
    const float* bias   = (const float*)d_in[1];
    const float* ln1_g  = (const float*)d_in[2];
    const float* ln1_b  = (const float*)d_in[3];
    const float* W_attn = (const float*)d_in[4];
    const float* b_attn = (const float*)d_in[5];
    const float* W_o    = (const float*)d_in[6];
    const float* b_o    = (const float*)d_in[7];
    const float* W_bias = (const float*)d_in[8];
    const float* b_bias = (const float*)d_in[9];
    const float* ln2_g  = (const float*)d_in[10];
    const float* ln2_b  = (const float*)d_in[11];
    const float* W_fc   = (const float*)d_in[12];
    const float* b_fc   = (const float*)d_in[13];
    const float* W_fc2  = (const float*)d_in[14];
    const float* b_fc2  = (const float*)d_in[15];
    float* out = (float*)d_out;

    __nv_bfloat16 *psa, *pact2, *pwt, *pqkv2;
    float *ppos, *px2;
    cudaGetSymbolAddress((void**)&psa,   g_sa);
    cudaGetSymbolAddress((void**)&pqkv2, g_qkv2);
    cudaGetSymbolAddress((void**)&ppos,  g_pos);
    cudaGetSymbolAddress((void**)&px2,   g_x2);
    cudaGetSymbolAddress((void**)&pact2, g_act2);
    cudaGetSymbolAddress((void**)&pwt,   g_wt);

    const int GSMEM = 3 * 32768;  // 96KB
    cudaFuncSetAttribute(mma_gemm<1>, cudaFuncAttributeMaxDynamicSharedMemorySize, GSMEM);
    cudaFuncSetAttribute(mma_gemm<2>, cudaFuncAttributeMaxDynamicSharedMemorySize, GSMEM);
    cudaFuncSetAttribute(mma_gemm<3>, cudaFuncAttributeMaxDynamicSharedMemorySize, GSMEM);
    cudaFuncSetAttribute(attn_tc_kernel, cudaFuncAttributeMaxDynamicSharedMemorySize, SM_ATTN_TOTAL);

    // 1) LN1 -> split
    ln_split_kernel<<<MR, 256>>>(x, ln1_g, ln1_b, psa);
    // 2) QKV = h @ W_attn + b_attn -> split q/k/v planes
    transpose_split_kernel<<<dim3(3072/32, 1024/32), 256>>>(W_attn, pwt, 1024, 3072);
    mma_gemm<3><<<dim3(3072/128, MR/128), 256, GSMEM>>>(psa, pwt, b_attn, nullptr, pqkv2, 3072, 3072);
    // 3) positional bias projection
    posbias_kernel<<<(TT * TT) / 256, 256>>>(bias, W_bias, b_bias, ppos);
    // 4) tensor-core attention -> split y
    attn_tc_kernel<<<BB * NHD * (TT / 64), 256, SM_ATTN_TOTAL>>>(pqkv2, ppos, psa);
    // 5) x2 = x + y @ W_o + b_o
    transpose_split_kernel<<<dim3(1024/32, 1024/32), 256>>>(W_o, pwt, 1024, 1024);
    mma_gemm<2><<<dim3(1024/128, MR/128), 256, GSMEM>>>(psa, pwt, b_o, x, px2, 1024, 3072);
    // 6) LN2 -> split
    ln_split_kernel<<<MR, 256>>>(px2, ln2_g, ln2_b, psa);
    // 7) act = gelu(h2 @ W_fc + b_fc) -> split
    transpose_split_kernel<<<dim3(4096/32, 1024/32), 256>>>(W_fc, pwt, 1024, 4096);
    mma_gemm<1><<<dim3(4096/128, MR/128), 256, GSMEM>>>(psa, pwt, b_fc, nullptr, pact2, 4096, 3072);
    // 8) out = x2 + act @ W_fc2 + b_fc2
    transpose_split_kernel<<<dim3(1024/32, 4096/32), 256>>>(W_fc2, pwt, 4096, 1024);
    mma_gemm<2><<<dim3(1024/128, MR/128), 256, GSMEM>>>(pact2, pwt, b_fc2, px2, out, 1024, 12288);
}